// round 7
// baseline (speedup 1.0000x reference)
#include <cuda_runtime.h>
#include <cuda_bf16.h>
#include <cstdint>

// ---------------- problem constants ----------------
#define IN_CH   256
#define BATCH   8
#define KF      2304            // 9*256
#define NOUT    512
#define L2D     1024
#define MROWS   (BATCH * L2D)   // 8192
#define NCHK    (KF / 64)       // 36 k-chunks of 64

// GEMM tiling: CTA 128(M) x 128(N), 8 warps (2m x 4n) of 64x32
#define NS   4                  // cp.async pipeline stages
#define TSZA (128 * 128)        // 16KB: 128 rows x 128B [hi64|lo64]
#define TSZB (128 * 128)        // 16KB
#define STAGE (TSZA + TSZB)     // 32KB
#define SMEM_TOTAL (NS * STAGE) // 128KB

// quantization: v ~= delta * (128*ah + al), ah,al int8 (al in [-64,63])
#define INVA   (16384.0f / 6.0f)
#define INVB   (16384.0f / 0.0464f)
#define OSCALE ((6.0f / 16384.0f) * (0.0464f / 16384.0f) * 128.0f)

// scratch (__device__ globals: allocation-free rule)
// layout: per (row r, k-chunk c of 64): 128B = [ah[64] | al[64]]
__device__ __align__(16) int8_t g_A[(size_t)MROWS * NCHK * 128];
__device__ __align__(16) int8_t g_B[(size_t)NOUT * NCHK * 128];

// ---------------- helpers ----------------
__device__ __forceinline__ void qsplit_store(int8_t* p, float v, float inv) {
    int q = __float2int_rn(v * inv);
    q = q < -16384 ? -16384 : (q > 16319 ? 16319 : q);
    int ah = (q + 64) >> 7;            // rounding split: al zero-mean
    int al = q - (ah << 7);            // in [-64, 63]
    p[0]  = (int8_t)ah;
    p[64] = (int8_t)al;
}
__device__ __forceinline__ void cpa16(uint32_t dst, const void* src) {
    asm volatile("cp.async.cg.shared.global [%0], [%1], 16;" :: "r"(dst), "l"(src));
}
#define CP_COMMIT() asm volatile("cp.async.commit_group;" ::: "memory")
#define CP_WAITN()  asm volatile("cp.async.wait_group %0;" :: "n"(NS - 2) : "memory")

// swizzled smem: addr(row, byte b) = row*128 + ((b/16 ^ row%8)*16) + b%16
__device__ __forceinline__ uint32_t ld8x4(const char* base, int row, int b) {
    return *(const uint32_t*)(base + row * 128 + (((b >> 4) ^ (row & 7)) << 4) + (b & 15));
}
__device__ __forceinline__ void mma_s8(int* c, const uint32_t* a, const uint32_t* b) {
    asm volatile(
        "mma.sync.aligned.m16n8k32.row.col.s32.s8.s8.s32 "
        "{%0,%1,%2,%3}, {%4,%5,%6,%7}, {%8,%9}, {%0,%1,%2,%3};"
        : "+r"(c[0]), "+r"(c[1]), "+r"(c[2]), "+r"(c[3])
        : "r"(a[0]), "r"(a[1]), "r"(a[2]), "r"(a[3]), "r"(b[0]), "r"(b[1]));
}

// ---------------------------------------------------------------------------
// Kernel 1: im2col -> int8 split chunked layout. grid (9, 256, 8).
// Flat A index i = (b*KF + f)*1024 + l; row r = i/KF, k = i%KF.
// ---------------------------------------------------------------------------
__global__ void im2col_kernel(const float* __restrict__ x) {
    const int dd = blockIdx.x, ci = blockIdx.y, b = blockIdx.z;
    const int oy = dd / 3 - 1, ox = dd % 3 - 1;          // uniform per block
    const float* xp = x + (((size_t)(b * IN_CH + ci)) << 10);
    const uint32_t ibase = ((uint32_t)(b * KF + ci * 9 + dd)) << 10;
    #pragma unroll
    for (int s = 0; s < 4; s++) {
        int l = threadIdx.x + s * 256;
        int h = l >> 5, w = l & 31;
        int y = h + oy, xw = w + ox;
        float v = 0.0f;
        if ((unsigned)y < 32u && (unsigned)xw < 32u) v = xp[(y << 5) + xw];
        uint32_t i = ibase + l;
        uint32_t r = i / KF, k = i % KF;
        qsplit_store(&g_A[(((size_t)r * NCHK + (k >> 6)) << 7) + (k & 63)], v, INVA);
    }
}

// ---------------------------------------------------------------------------
// Kernel 2: B^T expansion -> int8 split chunked. BT[co][k] = w[p][q][(j-m)&63]
// ---------------------------------------------------------------------------
__global__ void beffT_kernel(const float* __restrict__ wgt) {
    const int co = blockIdx.y;
    const int k = blockIdx.x * 256 + threadIdx.x;
    const int q = k >> 6, m = k & 63;
    const int p = co >> 6, j = co & 63;
    float v = wgt[((p * 36 + q) << 6) + ((j - m) & 63)];
    qsplit_store(&g_B[(((size_t)co * NCHK + (k >> 6)) << 7) + (k & 63)], v, INVB);
}

// ---------------------------------------------------------------------------
// Kernel 3: int8 split mma.sync GEMM, fused transpose store.
// CTA 128x128, 8 warps (2m x 4n) of 64x32, 4-stage cp.async.
// Per k32: S1 += ah*bh; S2 += ah*bl + al*bh  (al*bl dropped, zero-mean)
// C = OSCALE * (128*S1 + S2)
// ---------------------------------------------------------------------------
__global__ void __launch_bounds__(256, 1) gemm_kernel(float* __restrict__ out) {
    extern __shared__ char sm[];
    const int tid = threadIdx.x;
    const int lane = tid & 31;
    const int wid = tid >> 5;
    const int g = lane >> 2, t = lane & 3;
    const int wm = wid >> 2, wn = wid & 3;       // 2m x 4n
    const int bm = blockIdx.y * 128;
    const int bn = blockIdx.x * 128;

    int s1[4][4][4], s2[4][4][4];
    #pragma unroll
    for (int i = 0; i < 4; i++)
        #pragma unroll
        for (int j = 0; j < 4; j++)
            #pragma unroll
            for (int q = 0; q < 4; q++) { s1[i][j][q] = 0; s2[i][j][q] = 0; }

    auto load_chunk = [&](int c, int s) {
        char* As = sm + s * STAGE;
        char* Bs = As + TSZA;
        #pragma unroll
        for (int i = 0; i < 4; i++) {            // 128 rows x 8 x 16B each tile
            int id = tid + i * 256;
            int row = id >> 3, cj = id & 7;
            uint32_t swo = (uint32_t)(row * 128 + ((cj ^ (row & 7)) << 4));
            cpa16((uint32_t)__cvta_generic_to_shared(As + swo),
                  &g_A[(((size_t)(bm + row) * NCHK + c) << 7) + (cj << 4)]);
            cpa16((uint32_t)__cvta_generic_to_shared(Bs + swo),
                  &g_B[(((size_t)(bn + row) * NCHK + c) << 7) + (cj << 4)]);
        }
    };

    auto compute = [&](int s) {
        const char* As = sm + s * STAGE;
        const char* Bs = As + TSZA;
        #pragma unroll
        for (int kc = 0; kc < 2; kc++) {         // two k32 atoms per 64-chunk
            const int kb = kc * 32 + t * 4;      // hi byte base; lo at +64
            uint32_t ah[4][4], al[4][4], bh[4][2], bl[4][2];
            #pragma unroll
            for (int ma = 0; ma < 4; ma++) {
                int r0 = wm * 64 + ma * 16 + g;
                ah[ma][0] = ld8x4(As, r0,     kb);
                ah[ma][1] = ld8x4(As, r0 + 8, kb);
                ah[ma][2] = ld8x4(As, r0,     kb + 16);
                ah[ma][3] = ld8x4(As, r0 + 8, kb + 16);
                al[ma][0] = ld8x4(As, r0,     kb + 64);
                al[ma][1] = ld8x4(As, r0 + 8, kb + 64);
                al[ma][2] = ld8x4(As, r0,     kb + 80);
                al[ma][3] = ld8x4(As, r0 + 8, kb + 80);
            }
            #pragma unroll
            for (int na = 0; na < 4; na++) {
                int n0 = wn * 32 + na * 8 + g;
                bh[na][0] = ld8x4(Bs, n0, kb);
                bh[na][1] = ld8x4(Bs, n0, kb + 16);
                bl[na][0] = ld8x4(Bs, n0, kb + 64);
                bl[na][1] = ld8x4(Bs, n0, kb + 80);
            }
            #pragma unroll
            for (int ma = 0; ma < 4; ma++)
                #pragma unroll
                for (int na = 0; na < 4; na++) {
                    mma_s8(s1[ma][na], ah[ma], bh[na]);
                    mma_s8(s2[ma][na], ah[ma], bl[na]);
                    mma_s8(s2[ma][na], al[ma], bh[na]);
                }
        }
    };

    // prologue: prefetch NS-1 chunks
    #pragma unroll
    for (int s = 0; s < NS - 1; s++) { load_chunk(s, s); CP_COMMIT(); }

    for (int c = 0; c < NCHK; c++) {
        CP_WAITN();
        __syncthreads();
        const int cn = c + NS - 1;
        if (cn < NCHK) { load_chunk(cn, cn % NS); CP_COMMIT(); }
        compute(c % NS);
    }

    // epilogue: C[r][co] -> out[b][co][l2], r = b*1024 + l2
    #pragma unroll
    for (int ma = 0; ma < 4; ma++) {
        #pragma unroll
        for (int half = 0; half < 2; half++) {
            const int r = bm + wm * 64 + ma * 16 + g + half * 8;
            const int b = r >> 10;
            const int l2 = r & (L2D - 1);
            float* op = out + (((size_t)b * NOUT) << 10) + l2;
            #pragma unroll
            for (int na = 0; na < 4; na++) {
                const int co = bn + wn * 32 + na * 8 + t * 2;
                float v0 = fmaf((float)s1[ma][na][half * 2 + 0], 128.0f,
                                (float)s2[ma][na][half * 2 + 0]) * OSCALE;
                float v1 = fmaf((float)s1[ma][na][half * 2 + 1], 128.0f,
                                (float)s2[ma][na][half * 2 + 1]) * OSCALE;
                op[(size_t)co << 10]       = v0;
                op[(size_t)(co + 1) << 10] = v1;
            }
        }
    }
}

// ---------------------------------------------------------------------------
extern "C" void kernel_launch(void* const* d_in, const int* in_sizes, int n_in,
                              void* d_out, int out_size) {
    const float* x = (const float*)d_in[0];
    const float* w = (const float*)d_in[1];
    if (n_in >= 2 && in_sizes[0] == 8 * 36 * 64) {   // defensive swap by size
        const float* tp = x; x = w; w = tp;
    }
    float* out = (float*)d_out;

    cudaFuncSetAttribute(gemm_kernel, cudaFuncAttributeMaxDynamicSharedMemorySize, SMEM_TOTAL);

    im2col_kernel<<<dim3(9, IN_CH, BATCH), 256>>>(x);
    beffT_kernel<<<dim3(KF / 256, NOUT), 256>>>(w);
    gemm_kernel<<<dim3(NOUT / 128, MROWS / 128), 256, SMEM_TOTAL>>>(out);
    (void)out_size;
}

// round 8
// speedup vs baseline: 5.8784x; 5.8784x over previous
#include <cuda_runtime.h>
#include <cuda_fp16.h>
#include <cstdint>

// ---------------- problem constants ----------------
#define IN_CH   256
#define BATCH   8
#define KF      2304            // 9*256
#define NOUT    512
#define L2D     1024
#define MROWS   (BATCH * L2D)   // 8192
#define NCHK    (KF / 64)       // 36 k-chunks of 64 (64 fp16 = 128B row)

// GEMM tiling: CTA 128(M) x 256(N), 8 warps (2m x 4n) of 64x64
#define NS   4                  // cp.async pipeline stages
#define TSZA (128 * 128)        // 16KB: 128 rows x 128B
#define TSZB (256 * 128)        // 32KB: 256 rows x 128B
#define STAGE (TSZA + TSZB)     // 48KB
#define SMEM_TOTAL (NS * STAGE) // 192KB

// scratch (__device__ globals: allocation-free rule)
// chunked fp16: row r, k-chunk c (64 k) -> 128B at (r*NCHK + c)*128
__device__ __align__(16) __half g_A16[(size_t)MROWS * KF];
__device__ __align__(16) __half g_B16[(size_t)NOUT * KF];

// ---------------- helpers ----------------
__device__ __forceinline__ void cpa16(uint32_t dst, const void* src) {
    asm volatile("cp.async.cg.shared.global [%0], [%1], 16;" :: "r"(dst), "l"(src));
}
#define CP_COMMIT() asm volatile("cp.async.commit_group;" ::: "memory")
#define CP_WAITN()  asm volatile("cp.async.wait_group %0;" :: "n"(NS - 2) : "memory")

// swizzled smem row of 128B; w = 4-byte word index 0..31
__device__ __forceinline__ uint32_t lds32(const char* base, int row, int w) {
    return *(const uint32_t*)(base + row * 128 + (((w >> 2) ^ (row & 7)) << 4) + ((w & 3) << 2));
}
__device__ __forceinline__ void mma16f(float* c, const uint32_t* a, const uint32_t* b) {
    asm volatile(
        "mma.sync.aligned.m16n8k16.row.col.f32.f16.f16.f32 "
        "{%0,%1,%2,%3}, {%4,%5,%6,%7}, {%8,%9}, {%0,%1,%2,%3};"
        : "+f"(c[0]), "+f"(c[1]), "+f"(c[2]), "+f"(c[3])
        : "r"(a[0]), "r"(a[1]), "r"(a[2]), "r"(a[3]), "r"(b[0]), "r"(b[1]));
}

// ---------------------------------------------------------------------------
// Kernel 1: im2col -> chunked fp16. grid (9, 256, 8), 256 thr.
// Flat A index i = (b*KF + f)*1024 + l; r = i/KF, k = i%KF via uniform base
// decomposition + single carry (l < 1024 < KF so at most one wrap).
// ---------------------------------------------------------------------------
__global__ void im2col_kernel(const float* __restrict__ x) {
    const int dd = blockIdx.x, ci = blockIdx.y, b = blockIdx.z;
    const int oy = dd / 3 - 1, ox = dd % 3 - 1;          // uniform per block
    const float* xp = x + (((size_t)(b * IN_CH + ci)) << 10);
    const uint32_t ibase = ((uint32_t)(b * KF + ci * 9 + dd)) << 10;
    const uint32_t r0 = ibase / KF, k0 = ibase % KF;     // uniform per block
    #pragma unroll
    for (int s = 0; s < 4; s++) {
        int l = threadIdx.x + s * 256;
        int h = l >> 5, w = l & 31;
        int y = h + oy, xw = w + ox;
        float v = 0.0f;
        if ((unsigned)y < 32u && (unsigned)xw < 32u) v = xp[(y << 5) + xw];
        uint32_t k = k0 + l, r = r0;
        if (k >= KF) { k -= KF; r++; }
        g_A16[(((size_t)r * NCHK + (k >> 6)) << 6) + (k & 63)] = __float2half(v);
    }
}

// ---------------------------------------------------------------------------
// Kernel 2: B^T expansion -> chunked fp16. BT[co][k] = w[p][q][(j-m)&63]
// ---------------------------------------------------------------------------
__global__ void beffT_kernel(const float* __restrict__ wgt) {
    const int co = blockIdx.y;
    const int k = blockIdx.x * 256 + threadIdx.x;
    const int q = k >> 6, m = k & 63;
    const int p = co >> 6, j = co & 63;
    float v = wgt[((p * 36 + q) << 6) + ((j - m) & 63)];
    g_B16[(((size_t)co * NCHK + (k >> 6)) << 6) + (k & 63)] = __float2half(v);
}

// ---------------------------------------------------------------------------
// Kernel 3: fp16 mma.sync GEMM C[8192,512] = A @ B, fp32 accum, fused
// transpose store. CTA 128x256, 8 warps (2m x 4n) of 64x64, 4-stage cp.async.
// ---------------------------------------------------------------------------
__global__ void __launch_bounds__(256, 1) gemm_kernel(float* __restrict__ out) {
    extern __shared__ char sm[];
    const int tid = threadIdx.x;
    const int lane = tid & 31;
    const int wid = tid >> 5;
    const int g = lane >> 2, t = lane & 3;
    const int wm = wid >> 2, wn = wid & 3;       // 2m x 4n
    const int bm = blockIdx.y * 128;
    const int bn = blockIdx.x * 256;

    float acc[4][8][4];
    #pragma unroll
    for (int i = 0; i < 4; i++)
        #pragma unroll
        for (int j = 0; j < 8; j++)
            #pragma unroll
            for (int q = 0; q < 4; q++) acc[i][j][q] = 0.0f;

    auto load_chunk = [&](int c, int s) {
        char* As = sm + s * STAGE;
        char* Bs = As + TSZA;
        #pragma unroll
        for (int i = 0; i < 4; i++) {            // A: 128 rows x 8 x 16B
            int id = tid + i * 256;
            int row = id >> 3, cj = id & 7;
            uint32_t swo = (uint32_t)(row * 128 + ((cj ^ (row & 7)) << 4));
            cpa16((uint32_t)__cvta_generic_to_shared(As + swo),
                  &g_A16[(((size_t)(bm + row) * NCHK + c) << 6) + (cj << 3)]);
        }
        #pragma unroll
        for (int i = 0; i < 8; i++) {            // B: 256 rows x 8 x 16B
            int id = tid + i * 256;
            int row = id >> 3, cj = id & 7;
            uint32_t swo = (uint32_t)(row * 128 + ((cj ^ (row & 7)) << 4));
            cpa16((uint32_t)__cvta_generic_to_shared(Bs + swo),
                  &g_B16[(((size_t)(bn + row) * NCHK + c) << 6) + (cj << 3)]);
        }
    };

    auto compute = [&](int s) {
        const char* As = sm + s * STAGE;
        const char* Bs = As + TSZA;
        #pragma unroll
        for (int ka = 0; ka < 4; ka++) {         // 4 k16 atoms per 64-chunk
            const int kw = ka * 8;               // word base (8 words = 16 fp16)
            uint32_t a[4][4], bb[8][2];
            #pragma unroll
            for (int ma = 0; ma < 4; ma++) {
                int r0 = wm * 64 + ma * 16 + g;
                a[ma][0] = lds32(As, r0,     kw + t);
                a[ma][1] = lds32(As, r0 + 8, kw + t);
                a[ma][2] = lds32(As, r0,     kw + t + 4);
                a[ma][3] = lds32(As, r0 + 8, kw + t + 4);
            }
            #pragma unroll
            for (int na = 0; na < 8; na++) {
                int n0 = wn * 64 + na * 8 + g;
                bb[na][0] = lds32(Bs, n0, kw + t);
                bb[na][1] = lds32(Bs, n0, kw + t + 4);
            }
            #pragma unroll
            for (int ma = 0; ma < 4; ma++)
                #pragma unroll
                for (int na = 0; na < 8; na++)
                    mma16f(acc[ma][na], a[ma], bb[na]);
        }
    };

    // prologue: prefetch NS-1 chunks
    #pragma unroll
    for (int s = 0; s < NS - 1; s++) { load_chunk(s, s); CP_COMMIT(); }

    for (int c = 0; c < NCHK; c++) {
        CP_WAITN();
        __syncthreads();
        const int cn = c + NS - 1;
        if (cn < NCHK) { load_chunk(cn, cn % NS); CP_COMMIT(); }
        compute(c % NS);
    }

    // epilogue: C[r][co] -> out[b][co][l2], r = b*1024 + l2
    #pragma unroll
    for (int ma = 0; ma < 4; ma++) {
        #pragma unroll
        for (int half = 0; half < 2; half++) {
            const int r = bm + wm * 64 + ma * 16 + g + half * 8;
            const int b = r >> 10;
            const int l2 = r & (L2D - 1);
            float* op = out + (((size_t)b * NOUT) << 10) + l2;
            #pragma unroll
            for (int na = 0; na < 8; na++) {
                const int co = bn + wn * 64 + na * 8 + t * 2;
                op[(size_t)co << 10]       = acc[ma][na][half * 2 + 0];
                op[(size_t)(co + 1) << 10] = acc[ma][na][half * 2 + 1];
            }
        }
    }
}

// ---------------------------------------------------------------------------
extern "C" void kernel_launch(void* const* d_in, const int* in_sizes, int n_in,
                              void* d_out, int out_size) {
    const float* x = (const float*)d_in[0];
    const float* w = (const float*)d_in[1];
    if (n_in >= 2 && in_sizes[0] == 8 * 36 * 64) {   // defensive swap by size
        const float* tp = x; x = w; w = tp;
    }
    float* out = (float*)d_out;

    cudaFuncSetAttribute(gemm_kernel, cudaFuncAttributeMaxDynamicSharedMemorySize, SMEM_TOTAL);

    im2col_kernel<<<dim3(9, IN_CH, BATCH), 256>>>(x);
    beffT_kernel<<<dim3(KF / 256, NOUT), 256>>>(w);
    gemm_kernel<<<dim3(NOUT / 256, MROWS / 128), 256, SMEM_TOTAL>>>(out);
    (void)out_size;
}

// round 10
// speedup vs baseline: 6.3521x; 1.0806x over previous
#include <cuda_runtime.h>
#include <cuda_fp16.h>
#include <cstdint>

// ---------------- problem constants ----------------
#define IN_CH   256
#define BATCH   8
#define KF      2304            // 9*256
#define NOUT    512
#define L2D     1024
#define MROWS   (BATCH * L2D)   // 8192
#define NCHK    (KF / 64)       // 36 k-chunks of 64 (64 fp16 = 128B row)

// GEMM tiling: CTA 128(M) x 256(N), 8 warps (2m x 4n) of 64x64
#define NS   4                  // cp.async pipeline stages
#define TSZA (128 * 128)        // 16KB: 128 rows x 128B
#define TSZB (256 * 128)        // 32KB: 256 rows x 128B
#define STAGE (TSZA + TSZB)     // 48KB
#define SMEM_TOTAL (NS * STAGE) // 192KB

// scratch (__device__ globals: allocation-free rule)
// chunked fp16: row r, k-chunk c (64 k) -> 128B at (r*NCHK + c)*128
__device__ __align__(16) __half g_A16[(size_t)MROWS * KF];
__device__ __align__(16) __half g_B16[(size_t)NOUT * KF];

// ---------------- helpers ----------------
__device__ __forceinline__ uint32_t h2u(__half2 h) {
    uint32_t u;
    __builtin_memcpy(&u, &h, 4);
    return u;
}
__device__ __forceinline__ void cpa16(uint32_t dst, const void* src) {
    asm volatile("cp.async.cg.shared.global [%0], [%1], 16;" :: "r"(dst), "l"(src));
}
#define CP_COMMIT() asm volatile("cp.async.commit_group;" ::: "memory")
#define CP_WAITN()  asm volatile("cp.async.wait_group %0;" :: "n"(NS - 2) : "memory")

// swizzled smem row of 128B; w = 4-byte word index 0..31
__device__ __forceinline__ uint32_t lds32(const char* base, int row, int w) {
    return *(const uint32_t*)(base + row * 128 + (((w >> 2) ^ (row & 7)) << 4) + ((w & 3) << 2));
}
__device__ __forceinline__ void mma16f(float* c, const uint32_t* a, const uint32_t* b) {
    asm volatile(
        "mma.sync.aligned.m16n8k16.row.col.f32.f16.f16.f32 "
        "{%0,%1,%2,%3}, {%4,%5,%6,%7}, {%8,%9}, {%0,%1,%2,%3};"
        : "+f"(c[0]), "+f"(c[1]), "+f"(c[2]), "+f"(c[3])
        : "r"(a[0]), "r"(a[1]), "r"(a[2]), "r"(a[3]), "r"(b[0]), "r"(b[1]));
}

// ---------------------------------------------------------------------------
// Kernel 1: im2col -> chunked fp16, 4 elems/thread, one 8B store.
// grid (9, 256, 8), 256 thr. Flat A index i = (b*KF + f)*1024 + l.
// k0 = ibase % KF is a multiple of 1024, so k = k0 + l keeps l's mod-4
// phase: 4-groups are 8B-aligned, never cross a 64-chunk or the KF wrap.
// ---------------------------------------------------------------------------
__global__ void im2col_kernel(const float* __restrict__ x) {
    const int dd = blockIdx.x, ci = blockIdx.y, b = blockIdx.z;
    const int oy = dd / 3 - 1, ox = dd % 3 - 1;          // uniform per block
    const float* xp = x + (((size_t)(b * IN_CH + ci)) << 10);
    const uint32_t ibase = ((uint32_t)(b * KF + ci * 9 + dd)) << 10;
    const uint32_t r0 = ibase / KF, k0 = ibase % KF;     // uniform per block

    const int l = threadIdx.x << 2;                      // 0,4,...,1020
    const int h = l >> 5, w = l & 31;                    // w multiple of 4
    const int y = h + oy;
    const bool yok = (unsigned)y < 32u;
    const float* rowp = xp + (y << 5) + (w + ox);
    float v[4];
    #pragma unroll
    for (int e = 0; e < 4; e++) {
        int xw = w + ox + e;
        v[e] = (yok && (unsigned)xw < 32u) ? rowp[e] : 0.0f;
    }
    uint32_t k = k0 + (uint32_t)l, r = r0;
    if (k >= KF) { k -= KF; r++; }
    uint2 pk;
    pk.x = h2u(__floats2half2_rn(v[0], v[1]));
    pk.y = h2u(__floats2half2_rn(v[2], v[3]));
    *(uint2*)&g_A16[(((size_t)r * NCHK + (k >> 6)) << 6) + (k & 63)] = pk;
}

// ---------------------------------------------------------------------------
// Kernel 2: B^T expansion -> chunked fp16. BT[co][k] = w[p][q][(j-m)&63]
// ---------------------------------------------------------------------------
__global__ void beffT_kernel(const float* __restrict__ wgt) {
    const int co = blockIdx.y;
    const int k = blockIdx.x * 256 + threadIdx.x;
    const int q = k >> 6, m = k & 63;
    const int p = co >> 6, j = co & 63;
    float v = wgt[((p * 36 + q) << 6) + ((j - m) & 63)];
    g_B16[(((size_t)co * NCHK + (k >> 6)) << 6) + (k & 63)] = __float2half(v);
}

// ---------------------------------------------------------------------------
// Kernel 3: fp16 mma.sync GEMM C[8192,512] = A @ B, fp32 accum, fused
// transpose store. CTA 128x256, 8 warps (2m x 4n) of 64x64, 4-stage cp.async.
// ---------------------------------------------------------------------------
__global__ void __launch_bounds__(256, 1) gemm_kernel(float* __restrict__ out) {
    extern __shared__ char sm[];
    const int tid = threadIdx.x;
    const int lane = tid & 31;
    const int wid = tid >> 5;
    const int g = lane >> 2, t = lane & 3;
    const int wm = wid >> 2, wn = wid & 3;       // 2m x 4n
    const int bm = blockIdx.y * 128;
    const int bn = blockIdx.x * 256;

    float acc[4][8][4];
    #pragma unroll
    for (int i = 0; i < 4; i++)
        #pragma unroll
        for (int j = 0; j < 8; j++)
            #pragma unroll
            for (int q = 0; q < 4; q++) acc[i][j][q] = 0.0f;

    auto load_chunk = [&](int c, int s) {
        char* As = sm + s * STAGE;
        char* Bs = As + TSZA;
        #pragma unroll
        for (int i = 0; i < 4; i++) {            // A: 128 rows x 8 x 16B
            int id = tid + i * 256;
            int row = id >> 3, cj = id & 7;
            uint32_t swo = (uint32_t)(row * 128 + ((cj ^ (row & 7)) << 4));
            cpa16((uint32_t)__cvta_generic_to_shared(As + swo),
                  &g_A16[(((size_t)(bm + row) * NCHK + c) << 6) + (cj << 3)]);
        }
        #pragma unroll
        for (int i = 0; i < 8; i++) {            // B: 256 rows x 8 x 16B
            int id = tid + i * 256;
            int row = id >> 3, cj = id & 7;
            uint32_t swo = (uint32_t)(row * 128 + ((cj ^ (row & 7)) << 4));
            cpa16((uint32_t)__cvta_generic_to_shared(Bs + swo),
                  &g_B16[(((size_t)(bn + row) * NCHK + c) << 6) + (cj << 3)]);
        }
    };

    auto compute = [&](int s) {
        const char* As = sm + s * STAGE;
        const char* Bs = As + TSZA;
        #pragma unroll
        for (int ka = 0; ka < 4; ka++) {         // 4 k16 atoms per 64-chunk
            const int kw = ka * 8;               // word base (8 words = 16 fp16)
            uint32_t a[4][4], bb[8][2];
            #pragma unroll
            for (int ma = 0; ma < 4; ma++) {
                int r0 = wm * 64 + ma * 16 + g;
                a[ma][0] = lds32(As, r0,     kw + t);
                a[ma][1] = lds32(As, r0 + 8, kw + t);
                a[ma][2] = lds32(As, r0,     kw + t + 4);
                a[ma][3] = lds32(As, r0 + 8, kw + t + 4);
            }
            #pragma unroll
            for (int na = 0; na < 8; na++) {
                int n0 = wn * 64 + na * 8 + g;
                bb[na][0] = lds32(Bs, n0, kw + t);
                bb[na][1] = lds32(Bs, n0, kw + t + 4);
            }
            #pragma unroll
            for (int ma = 0; ma < 4; ma++)
                #pragma unroll
                for (int na = 0; na < 8; na++)
                    mma16f(acc[ma][na], a[ma], bb[na]);
        }
    };

    // prologue: prefetch NS-1 chunks
    #pragma unroll
    for (int s = 0; s < NS - 1; s++) { load_chunk(s, s); CP_COMMIT(); }

    for (int c = 0; c < NCHK; c++) {
        CP_WAITN();
        __syncthreads();
        const int cn = c + NS - 1;
        if (cn < NCHK) { load_chunk(cn, cn % NS); CP_COMMIT(); }
        compute(c % NS);
    }

    // epilogue: C[r][co] -> out[b][co][l2], r = b*1024 + l2
    #pragma unroll
    for (int ma = 0; ma < 4; ma++) {
        #pragma unroll
        for (int half = 0; half < 2; half++) {
            const int r = bm + wm * 64 + ma * 16 + g + half * 8;
            const int b = r >> 10;
            const int l2 = r & (L2D - 1);
            float* op = out + (((size_t)b * NOUT) << 10) + l2;
            #pragma unroll
            for (int na = 0; na < 8; na++) {
                const int co = bn + wn * 64 + na * 8 + t * 2;
                op[(size_t)co << 10]       = acc[ma][na][half * 2 + 0];
                op[(size_t)(co + 1) << 10] = acc[ma][na][half * 2 + 1];
            }
        }
    }
}

// ---------------------------------------------------------------------------
extern "C" void kernel_launch(void* const* d_in, const int* in_sizes, int n_in,
                              void* d_out, int out_size) {
    const float* x = (const float*)d_in[0];
    const float* w = (const float*)d_in[1];
    if (n_in >= 2 && in_sizes[0] == 8 * 36 * 64) {   // defensive swap by size
        const float* tp = x; x = w; w = tp;
    }
    float* out = (float*)d_out;

    cudaFuncSetAttribute(gemm_kernel, cudaFuncAttributeMaxDynamicSharedMemorySize, SMEM_TOTAL);

    im2col_kernel<<<dim3(9, IN_CH, BATCH), 256>>>(x);
    beffT_kernel<<<dim3(KF / 256, NOUT), 256>>>(w);
    gemm_kernel<<<dim3(NOUT / 256, MROWS / 128), 256, SMEM_TOTAL>>>(out);
    (void)out_size;
}